// round 7
// baseline (speedup 1.0000x reference)
#include <cuda_runtime.h>
#include <mma.h>
#include <math.h>

using namespace nvcuda;

#define B_ 2
#define T_ 512
#define C_ 263
#define D_ 512
#define F_ 257          // T/2 + 1
#define K_TOP 51        // int(512 * 0.1)
#define WIN_ 24
#define KPAD 272        // 263 padded to multiple of 16 (zero-filled)

// packed spectrum: row f in [0,256] = re_f ; row 256+f for f in [1,255] = im_f
#define MR 512
#define KI 512

// ---------------- scratch (static device memory; no allocation) ----------------
__device__ float g_ex [B_*T_*D_];
__device__ float g_h  [B_*T_*D_];
__device__ float g_mtd[B_*T_*D_];
__device__ float g_cf [B_*MR*D_];
__device__ float g_fin[B_*KI*D_];
__device__ float g_score[B_*T_];
__device__ float g_mag  [B_*F_];
__device__ int   g_tidx[B_*K_TOP];
__device__ int   g_fidx[B_*K_TOP];
__device__ unsigned char g_tmask[B_*T_];
__device__ unsigned char g_fmask[B_*F_];
__device__ unsigned char g_tm   [B_*T_];
__device__ float g_costab[512];
__device__ float g_sintab[512];
__device__ float g_pe[T_*D_];
__device__ double g_div[256];
__device__ float g_xpad[B_*T_*KPAD + 64];
__device__ float g_wpad[D_*KPAD + 64];
__device__ float g_wdft [MR*T_];
__device__ float g_widft[T_*KI];

// ---------------- stream/event (created in static ctor, pre-checkpoint) --------
static cudaStream_t g_sB = nullptr;
static cudaEvent_t g_evStart = nullptr, g_evFork = nullptr, g_evJoin = nullptr;
namespace {
struct StreamInit {
    StreamInit() {
        cudaStreamCreateWithFlags(&g_sB, cudaStreamNonBlocking);
        cudaEventCreateWithFlags(&g_evStart, cudaEventDisableTiming);
        cudaEventCreateWithFlags(&g_evFork, cudaEventDisableTiming);
        cudaEventCreateWithFlags(&g_evJoin, cudaEventDisableTiming);
    }
};
StreamInit g_streamInit;
}

// ---------------- table init ----------------------------------------------------
__global__ void init_div_kernel() {
    int i = threadIdx.x;
    if (i < 256) {
        g_div[i] = exp(-(double)(2 * i) * (9.210340371976184 / 512.0));
    }
    if (i < 512) {
        float s, c;
        sincospif((float)i / 256.0f, &s, &c);
        g_costab[i] = c; g_sintab[i] = s;
    }
}

__global__ void init_pe_kernel() {
    int i = blockIdx.x * blockDim.x + threadIdx.x;
    if (i >= T_ * D_) return;
    int t = i / D_, d = i % D_;
    double arg = (double)t * g_div[d >> 1];
    const double PI2 = 6.283185307179586476925286766559;
    double q = rint(arg * (1.0 / PI2));
    float rf = (float)(arg - q * PI2);
    g_pe[i] = (d & 1) ? cosf(rf) : sinf(rf);
}

__global__ void init_wdft_kernel() {
    int i = blockIdx.x * blockDim.x + threadIdx.x;
    const int n1 = MR * T_;
    if (i < n1) {
        int r = i >> 9, t = i & 511;
        float s, c;
        if (r <= 256) {
            sincospif((float)((r * t) & 511) / 256.0f, &s, &c);
            g_wdft[i] = c;
        } else {
            sincospif((float)(((r - 256) * t) & 511) / 256.0f, &s, &c);
            g_wdft[i] = -s;
        }
    } else {
        int j = i - n1;
        if (j < T_ * KI) {
            int t = j >> 9, c = j & 511;
            float s, cc;
            if (c <= 256) {
                float w = (c == 0 || c == 256) ? (1.f / 512.f) : (2.f / 512.f);
                sincospif((float)((c * t) & 511) / 256.0f, &s, &cc);
                g_widft[j] = w * cc;
            } else {
                int f = c - 256;
                sincospif((float)((f * t) & 511) / 256.0f, &s, &cc);
                g_widft[j] = -(2.f / 512.f) * s;
            }
        }
    }
}

__global__ void pad_kernel(const float* __restrict__ x, const float* __restrict__ w) {
    int i = blockIdx.x * blockDim.x + threadIdx.x;
    const int n1 = B_ * T_ * KPAD;
    if (i < n1) {
        int r = i / KPAD, c = i % KPAD;
        g_xpad[i] = (c < C_) ? x[r * C_ + c] : 0.f;
    } else {
        int j = i - n1;
        if (j < D_ * KPAD) {
            int r = j / KPAD, c = j % KPAD;
            g_wpad[j] = (c < C_) ? w[r * C_ + c] : 0.f;
        }
    }
}

// ---------------- tensor-core GEMM: 3xTF32 split (fp32-level accuracy) ---------
// 64x64 tile, 256 threads (8 warps, 2 n x 4 m), each warp 16x32 (2 m16n16k8 frags)
#define EPI_NONE    0
#define EPI_PE      2
#define EPI_GELU    3
#define EPI_SIGMASK 4
#define EPI_TMSEL   5

#define ALD 24          // A smem ld (mult of 8)
#define BLD 72          // B smem ld (mult of 8)
#define CLD 72          // C smem ld (mult of 8)

// C[M, N] = A[M, K](lda) * B(^T).  K mult of 16, M mult of 64 (per batch).
// BKN=0: B is [N][K] row-major (ldb = row stride), N mult of 64  -> A*B^T
// BKN=1: B is [K][ldb] row-major, logical [K][N]; cols >= ldb read as 0 -> A*B
template <int EPI, int BKN>
__global__ void __launch_bounds__(256) wgemm_kernel(
        const float* __restrict__ A, int lda, long sA,
        const float* __restrict__ B, int ldb, long sB,
        float* __restrict__ Cm, int ldc, long sC, int N, int K,
        const float* __restrict__ bias,
        const unsigned char* __restrict__ mask,
        const float* __restrict__ token,
        const float* __restrict__ e1, const float* __restrict__ e2,
        const float* __restrict__ e3, const float* __restrict__ e4)
{
    A += (long)blockIdx.z * sA;
    B += (long)blockIdx.z * sB;
    Cm += (long)blockIdx.z * sC;

    __shared__ float Ah[64][ALD], Al[64][ALD];
    __shared__ float Bh[16][BLD], Bl[16][BLD];
    __shared__ float Cs[64][CLD];

    int tid = threadIdx.x;
    int wid = tid >> 5;
    int wm = wid >> 1;            // 0..3 -> m offset wm*16
    int wn = wid & 1;             // 0..1 -> n offset wn*32
    int bm = blockIdx.y * 64;
    int bn = blockIdx.x * 64;

    wmma::fragment<wmma::accumulator, 16, 16, 8, float> c0, c1;
    wmma::fill_fragment(c0, 0.f);
    wmma::fill_fragment(c1, 0.f);

    for (int k0 = 0; k0 < K; k0 += 16) {
        {   // A tile: 64 rows x 16 k, float4 per thread, split hi/lo
            int row = tid >> 2, kq = (tid & 3) * 4;
            float4 v = *(const float4*)&A[(size_t)(bm + row) * lda + k0 + kq];
            float f[4] = {v.x, v.y, v.z, v.w};
            #pragma unroll
            for (int j = 0; j < 4; j++) {
                float hi = wmma::__float_to_tf32(f[j]);
                Ah[row][kq + j] = hi;
                Al[row][kq + j] = f[j] - hi;
            }
        }
        if (BKN) {  // B [K][ldb]: 16 x 64 tile
            int kk = tid >> 4, nn = (tid & 15) * 4;
            float4 v = make_float4(0.f, 0.f, 0.f, 0.f);
            if (bn + nn < ldb)
                v = *(const float4*)&B[(size_t)(k0 + kk) * ldb + bn + nn];
            float f[4] = {v.x, v.y, v.z, v.w};
            #pragma unroll
            for (int j = 0; j < 4; j++) {
                float hi = wmma::__float_to_tf32(f[j]);
                Bh[kk][nn + j] = hi;
                Bl[kk][nn + j] = f[j] - hi;
            }
        } else {    // B [N][K]: load transposed into [k][n]
            int row = tid >> 2, kq = (tid & 3) * 4;
            float4 v = *(const float4*)&B[(size_t)(bn + row) * ldb + k0 + kq];
            float f[4] = {v.x, v.y, v.z, v.w};
            #pragma unroll
            for (int j = 0; j < 4; j++) {
                float hi = wmma::__float_to_tf32(f[j]);
                Bh[kq + j][row] = hi;
                Bl[kq + j][row] = f[j] - hi;
            }
        }
        __syncthreads();

        #pragma unroll
        for (int kc = 0; kc < 16; kc += 8) {
            wmma::fragment<wmma::matrix_a, 16, 16, 8, wmma::precision::tf32, wmma::row_major> ah, al;
            wmma::load_matrix_sync(ah, &Ah[wm * 16][kc], ALD);
            wmma::load_matrix_sync(al, &Al[wm * 16][kc], ALD);
            wmma::fragment<wmma::matrix_b, 16, 16, 8, wmma::precision::tf32, wmma::row_major> bh, bl;

            wmma::load_matrix_sync(bh, &Bh[kc][wn * 32], BLD);
            wmma::load_matrix_sync(bl, &Bl[kc][wn * 32], BLD);
            wmma::mma_sync(c0, al, bh, c0);
            wmma::mma_sync(c0, ah, bl, c0);
            wmma::mma_sync(c0, ah, bh, c0);

            wmma::load_matrix_sync(bh, &Bh[kc][wn * 32 + 16], BLD);
            wmma::load_matrix_sync(bl, &Bl[kc][wn * 32 + 16], BLD);
            wmma::mma_sync(c1, al, bh, c1);
            wmma::mma_sync(c1, ah, bl, c1);
            wmma::mma_sync(c1, ah, bh, c1);
        }
        __syncthreads();
    }

    // stage accumulators through smem, then elementwise epilogue
    wmma::store_matrix_sync(&Cs[wm * 16][wn * 32], c0, CLD, wmma::mem_row_major);
    wmma::store_matrix_sync(&Cs[wm * 16][wn * 32 + 16], c1, CLD, wmma::mem_row_major);
    __syncthreads();

    #pragma unroll
    for (int it = 0; it < 16; it++) {
        int idx = tid + it * 256;         // 0..4095
        int r = idx >> 6, col0 = idx & 63;
        int row = bm + r;
        int col = bn + col0;
        if (col >= N) continue;
        float v = Cs[r][col0];
        if (EPI == EPI_PE) {
            v += bias[col];
            v += g_pe[(row & (T_ - 1)) * D_ + col];
        } else if (EPI == EPI_GELU) {
            v += bias[col];
            v = 0.5f * v * (1.f + erff(v * 0.70710678118654752f));
        } else if (EPI == EPI_SIGMASK) {
            v += bias[col];
            v = 1.f / (1.f + expf(-v));
            if (mask[row]) v = token[col];
        } else if (EPI == EPI_TMSEL) {
            if (!mask[row]) {
                float m = v, a = 0.f;
                for (int dd = 0; dd < D_; dd++) {
                    float u = fmaf(m, e1[dd], e2[dd]);
                    float g = 0.5f * u * (1.f + erff(u * 0.70710678118654752f));
                    a = fmaf(g, e3[dd], a);
                }
                v = 1.f / (1.f + expf(-(a + e4[0])));
            }
        }
        Cm[(size_t)row * ldc + col] = v;
    }
}

// ---------------- windowed-variance score: one block per (b,t) -----------------
__global__ void score_kernel() {
    int bt = blockIdx.x;
    int b = bt >> 9, t = bt & 511;
    int tid = threadIdx.x;            // 256
    int t0 = t - (WIN_ - 1); if (t0 < 0) t0 = 0;
    float denom = (float)((t + 1 < WIN_) ? (t + 1) : WIN_);
    float num = 0.f, den = 0.f;
    for (int d = tid; d < D_; d += 256) {
        float s1 = 0.f, s2 = 0.f;
        const float* p = &g_ex[((size_t)b * T_ + t0) * D_ + d];
        for (int tt = t0; tt <= t; tt++) {
            float v = *p; p += D_;
            s1 += v;
            s2 = fmaf(v, v, s2);
        }
        float m1 = s1 / denom;
        num += s2 / denom - m1 * m1;
        den += m1;
    }
    __shared__ float sn[256], sd[256];
    sn[tid] = num; sd[tid] = den; __syncthreads();
    for (int s = 128; s > 0; s >>= 1) {
        if (tid < s) { sn[tid] += sn[tid + s]; sd[tid] += sd[tid + s]; }
        __syncthreads();
    }
    if (tid == 0) g_score[bt] = sn[0] / (sd[0] + 1e-6f);
}

// ---------------- top-k via rank selection (lax.top_k stable-desc semantics) ---
__global__ void topk_kernel(const float* __restrict__ vals, int n, int k,
                            int* __restrict__ idx_out,
                            unsigned char* __restrict__ mask_out,
                            float* __restrict__ outf)
{
    int b = blockIdx.x;
    int tid = threadIdx.x;            // 512
    __shared__ float v[512];
    for (int i = tid; i < n; i += blockDim.x) v[i] = vals[b * n + i];
    if (tid < n) mask_out[b * n + tid] = 0;
    __syncthreads();
    if (tid < n) {
        float x = v[tid];
        int rank = 0;
        for (int j = 0; j < n; j++) {
            float y = v[j];
            rank += (y > x) || (y == x && j < tid);
        }
        if (rank < k) {
            idx_out[b * k + rank] = tid;
            outf[b * k + rank] = (float)tid;
            mask_out[b * n + tid] = 1;
        }
    }
}

// ---------------- magnitude mean over d: one block per (b,f) -------------------
__global__ void mag_kernel() {
    int bf = blockIdx.x;
    int b = bf / F_, f = bf % F_;
    int d = threadIdx.x;              // 512
    float cr = g_cf[((size_t)b * MR + f) * D_ + d];
    float ci = (f == 0 || f == 256) ? 0.f
             : g_cf[((size_t)b * MR + 256 + f) * D_ + d];
    float m = sqrtf(cr * cr + ci * ci);
    __shared__ float red[512];
    red[d] = m; __syncthreads();
    for (int s = 256; s > 0; s >>= 1) {
        if (d < s) red[d] += red[d + s];
        __syncthreads();
    }
    if (d == 0) g_mag[bf] = red[0] * (1.f / 512.f);
}

// ---------------- time-domain mask tm = irfft(fmask) != 0 ----------------------
__global__ void tm_kernel() {
    int b = blockIdx.x;
    int t = threadIdx.x;              // 512
    const unsigned char* fm = &g_fmask[b * F_];
    float y = fm[0] ? 1.f : 0.f;
    for (int f = 1; f < 256; f++)
        if (fm[f]) y += 2.f * g_costab[(f * t) & 511];
    if (fm[256]) y += (t & 1) ? -1.f : 1.f;
    g_tm[b * T_ + t] = (y != 0.f) ? 1 : 0;
}

// ---------------- build masked packed spectrum for irfft GEMM ------------------
__global__ void buildfin_kernel(const float* __restrict__ f_tok_re,
                                const float* __restrict__ f_tok_im) {
    int i = blockIdx.x * blockDim.x + threadIdx.x;
    if (i >= B_ * KI * D_) return;
    int b = i / (KI * D_);
    int rem = i - b * KI * D_;
    int r = rem >> 9, d = rem & 511;
    int f = (r <= 256) ? r : (r - 256);
    float v;
    if (g_fmask[b * F_ + f]) v = (r <= 256) ? f_tok_re[d] : f_tok_im[d];
    else                     v = g_cf[(size_t)b * MR * D_ + rem];
    g_fin[i] = v;
}

// ---------------- launch ----------------
extern "C" void kernel_launch(void* const* d_in, const int* in_sizes, int n_in,
                              void* d_out, int out_size) {
    const float* x        = (const float*)d_in[0];
    const float* W_emb    = (const float*)d_in[1];
    const float* b_emb    = (const float*)d_in[2];
    const float* t_token  = (const float*)d_in[3];
    const float* tW1      = (const float*)d_in[4];
    const float* tb1      = (const float*)d_in[5];
    const float* tW2      = (const float*)d_in[6];
    const float* tb2      = (const float*)d_in[7];
    const float* f_tok_re = (const float*)d_in[8];
    const float* f_tok_im = (const float*)d_in[9];
    const float* fW1      = (const float*)d_in[10];
    const float* fb1      = (const float*)d_in[11];
    const float* fW2      = (const float*)d_in[12];
    const float* fb2      = (const float*)d_in[13];
    float* out = (float*)d_out;

    // output packing: out_t [B,T,D] | tidx [B,51] | out_f [B,T,C] | fidx [B,51]
    float* out_t    = out;
    float* out_tidx = out + (size_t)B_ * T_ * D_;
    float* out_f    = out_tidx + B_ * K_TOP;
    float* out_fidx = out_f + (size_t)B_ * T_ * C_;

    float *p_ex, *p_h, *p_mtd, *p_score, *p_mag, *p_xpad, *p_wpad;
    float *p_wdft, *p_widft, *p_cf, *p_fin;
    int *p_tidx, *p_fidx;
    unsigned char *p_tmask, *p_fmask, *p_tm;
    cudaGetSymbolAddress((void**)&p_ex,    g_ex);
    cudaGetSymbolAddress((void**)&p_h,     g_h);
    cudaGetSymbolAddress((void**)&p_mtd,   g_mtd);
    cudaGetSymbolAddress((void**)&p_score, g_score);
    cudaGetSymbolAddress((void**)&p_mag,   g_mag);
    cudaGetSymbolAddress((void**)&p_xpad,  g_xpad);
    cudaGetSymbolAddress((void**)&p_wpad,  g_wpad);
    cudaGetSymbolAddress((void**)&p_wdft,  g_wdft);
    cudaGetSymbolAddress((void**)&p_widft, g_widft);
    cudaGetSymbolAddress((void**)&p_cf,    g_cf);
    cudaGetSymbolAddress((void**)&p_fin,   g_fin);
    cudaGetSymbolAddress((void**)&p_tidx,  g_tidx);
    cudaGetSymbolAddress((void**)&p_fidx,  g_fidx);
    cudaGetSymbolAddress((void**)&p_tmask, g_tmask);
    cudaGetSymbolAddress((void**)&p_fmask, g_fmask);
    cudaGetSymbolAddress((void**)&p_tm,    g_tm);

    if (!g_sB) {
        cudaStreamCreateWithFlags(&g_sB, cudaStreamNonBlocking);
        cudaEventCreateWithFlags(&g_evStart, cudaEventDisableTiming);
        cudaEventCreateWithFlags(&g_evFork, cudaEventDisableTiming);
        cudaEventCreateWithFlags(&g_evJoin, cudaEventDisableTiming);
    }

    // ---- legal capture fork at t=0: g_sB joins the capture via evStart ----
    cudaEventRecord(g_evStart, 0);
    cudaStreamWaitEvent(g_sB, g_evStart, 0);

    // DFT weight tables on g_sB (input-independent; overlaps prologue + GEMM1)
    init_wdft_kernel<<<(MR * T_ + T_ * KI + 255) / 256, 256, 0, g_sB>>>();

    // ---- prologue on stream 0 ----
    init_div_kernel<<<1, 512>>>();
    init_pe_kernel<<<(T_ * D_ + 255) / 256, 256>>>();
    pad_kernel<<<((B_ * T_ + D_) * KPAD + 255) / 256, 256>>>(x, W_emb);

    // ex = x * W_emb^T + b_emb + PE      (padded K=272)
    wgemm_kernel<EPI_PE, 0><<<dim3(D_ / 64, B_ * T_ / 64), 256>>>(
        p_xpad, KPAD, 0, p_wpad, KPAD, 0, p_ex, D_, 0, D_, KPAD,
        b_emb, nullptr, nullptr, nullptr, nullptr, nullptr, nullptr);

    // ---- fork: path B (frequency) continues on g_sB after ex is ready ----
    cudaEventRecord(g_evFork, 0);
    cudaStreamWaitEvent(g_sB, g_evFork, 0);
    {
        // cf[b] = Wdft[512,512] @ ex[b][512,512]   (packed re/im rows)
        wgemm_kernel<EPI_NONE, 1><<<dim3(D_ / 64, MR / 64, B_), 256, 0, g_sB>>>(
            p_wdft, T_, 0, p_ex, D_, (long)T_ * D_, p_cf, D_, (long)MR * D_, D_, T_,
            nullptr, nullptr, nullptr, nullptr, nullptr, nullptr, nullptr);
        mag_kernel<<<B_ * F_, 512, 0, g_sB>>>();
        topk_kernel<<<B_, 512, 0, g_sB>>>(p_mag, F_, K_TOP, p_fidx, p_fmask, out_fidx);
        tm_kernel<<<B_, 512, 0, g_sB>>>();
        buildfin_kernel<<<(B_ * KI * D_ + 255) / 256, 256, 0, g_sB>>>(f_tok_re, f_tok_im);
        // mtd[b] = Widft[512,512] @ fin[b][512,512]
        wgemm_kernel<EPI_NONE, 1><<<dim3(D_ / 64, T_ / 64, B_), 256, 0, g_sB>>>(
            p_widft, KI, 0, p_fin, D_, (long)KI * D_, p_mtd, D_, (long)T_ * D_, D_, KI,
            nullptr, nullptr, nullptr, nullptr, nullptr, nullptr, nullptr);
        // out_f = tmsel(mtd @ W_emb)   (fused mx + outf)
        wgemm_kernel<EPI_TMSEL, 1><<<dim3((C_ + 63) / 64, B_ * T_ / 64), 256, 0, g_sB>>>(
            p_mtd, D_, 0, p_wpad, KPAD, 0, out_f, C_, 0, C_, D_,
            nullptr, p_tm, nullptr, fW1, fb1, fW2, fb2);
        cudaEventRecord(g_evJoin, g_sB);
    }

    // ---- path A (temporal) on stream 0 ----
    score_kernel<<<B_ * T_, 256>>>();
    topk_kernel<<<B_, 512>>>(p_score, T_, K_TOP, p_tidx, p_tmask, out_tidx);
    // h = gelu(ex * tW1^T + tb1)
    wgemm_kernel<EPI_GELU, 0><<<dim3(D_ / 64, B_ * T_ / 64), 256>>>(
        p_ex, D_, 0, tW1, D_, 0, p_h, D_, 0, D_, D_,
        tb1, nullptr, nullptr, nullptr, nullptr, nullptr, nullptr);
    // out_t = tmask ? t_token : sigmoid(h * tW2^T + tb2)
    wgemm_kernel<EPI_SIGMASK, 0><<<dim3(D_ / 64, B_ * T_ / 64), 256>>>(
        p_h, D_, 0, tW2, D_, 0, out_t, D_, 0, D_, D_,
        tb2, p_tmask, t_token, nullptr, nullptr, nullptr, nullptr);

    // ---- join ----
    cudaStreamWaitEvent(0, g_evJoin, 0);
}

// round 8
// speedup vs baseline: 1.6158x; 1.6158x over previous
#include <cuda_runtime.h>
#include <math.h>

#define B_ 2
#define T_ 512
#define C_ 263
#define D_ 512
#define F_ 257          // T/2 + 1
#define K_TOP 51        // int(512 * 0.1)
#define WIN_ 24
#define KPAD 272        // 263 padded to multiple of 16 (zero-filled)

// packed spectrum: row f in [0,256] = re_f ; row 256+f for f in [1,255] = im_f
#define MR 512
#define KI 512
#define NDELTA 112      // max masked packed rows (<=102), padded to mult of 16

// ---------------- scratch (static device memory; no allocation) ----------------
__device__ float g_ex [B_*T_*D_];
__device__ float g_h  [B_*T_*D_];
__device__ float g_mtd[B_*T_*D_];
__device__ float g_cf [B_*MR*D_];
__device__ float g_delta[B_*NDELTA*D_];     // (token - cf) at masked packed rows
__device__ float g_wsub [B_*T_*NDELTA];     // gathered Widft columns
__device__ int   g_rowlist[B_*NDELTA];
__device__ float g_score[B_*T_];
__device__ float g_mag  [B_*F_];
__device__ int   g_tidx[B_*K_TOP];
__device__ int   g_fidx[B_*K_TOP];
__device__ unsigned char g_tmask[B_*T_];
__device__ unsigned char g_fmask[B_*F_];
__device__ unsigned char g_tm   [B_*T_];
__device__ float g_costab[512];
__device__ float g_sintab[512];
__device__ float g_pe[T_*D_];
__device__ double g_div[256];
__device__ float g_xpad[B_*T_*KPAD + 64];
__device__ float g_wpad[D_*KPAD + 64];
__device__ float g_wdft [MR*T_];
__device__ float g_widft[T_*KI];

// ---------------- stream/event (created in static ctor, pre-checkpoint) --------
static cudaStream_t g_sB = nullptr;
static cudaEvent_t g_evStart = nullptr, g_evFork = nullptr, g_evJoin = nullptr;
namespace {
struct StreamInit {
    StreamInit() {
        cudaStreamCreateWithFlags(&g_sB, cudaStreamNonBlocking);
        cudaEventCreateWithFlags(&g_evStart, cudaEventDisableTiming);
        cudaEventCreateWithFlags(&g_evFork, cudaEventDisableTiming);
        cudaEventCreateWithFlags(&g_evJoin, cudaEventDisableTiming);
    }
};
StreamInit g_streamInit;
}

// ---------------- table init ----------------------------------------------------
__global__ void init_div_kernel() {
    int i = threadIdx.x;
    if (i < 256) {
        g_div[i] = exp(-(double)(2 * i) * (9.210340371976184 / 512.0));
    }
    if (i < 512) {
        float s, c;
        sincospif((float)i / 256.0f, &s, &c);
        g_costab[i] = c; g_sintab[i] = s;
    }
}

// merged: PE table + pad x -> [B*T][272] + pad W_emb -> [D][272]
__global__ void prep_kernel(const float* __restrict__ x, const float* __restrict__ w) {
    int i = blockIdx.x * blockDim.x + threadIdx.x;
    const int nPE = T_ * D_;
    const int nX  = B_ * T_ * KPAD;
    if (i < nPE) {
        int t = i / D_, d = i % D_;
        double arg = (double)t * g_div[d >> 1];
        const double PI2 = 6.283185307179586476925286766559;
        double q = rint(arg * (1.0 / PI2));
        float rf = (float)(arg - q * PI2);
        g_pe[i] = (d & 1) ? cosf(rf) : sinf(rf);
    } else if (i < nPE + nX) {
        int j = i - nPE;
        int r = j / KPAD, c = j % KPAD;
        g_xpad[j] = (c < C_) ? x[r * C_ + c] : 0.f;
    } else {
        int j = i - nPE - nX;
        if (j < D_ * KPAD) {
            int r = j / KPAD, c = j % KPAD;
            g_wpad[j] = (c < C_) ? w[r * C_ + c] : 0.f;
        }
    }
}

// DFT weight tables (input-independent; identical twiddle values)
__global__ void init_wdft_kernel() {
    int i = blockIdx.x * blockDim.x + threadIdx.x;
    const int n1 = MR * T_;
    if (i < n1) {
        int r = i >> 9, t = i & 511;
        float s, c;
        if (r <= 256) {
            sincospif((float)((r * t) & 511) / 256.0f, &s, &c);
            g_wdft[i] = c;
        } else {
            sincospif((float)(((r - 256) * t) & 511) / 256.0f, &s, &c);
            g_wdft[i] = -s;
        }
    } else {
        int j = i - n1;
        if (j < T_ * KI) {
            int t = j >> 9, c = j & 511;
            float s, cc;
            if (c <= 256) {
                float w = (c == 0 || c == 256) ? (1.f / 512.f) : (2.f / 512.f);
                sincospif((float)((c * t) & 511) / 256.0f, &s, &cc);
                g_widft[j] = w * cc;
            } else {
                int f = c - 256;
                sincospif((float)((f * t) & 511) / 256.0f, &s, &cc);
                g_widft[j] = -(2.f / 512.f) * s;
            }
        }
    }
}

// ---------------- SGEMM v4: 64x64x16, 256 thr, 4x4/thr, double-buffered smem ---
#define EPI_NONE    0
#define EPI_PE      2
#define EPI_GELU    3
#define EPI_SIGMASK 4
#define EPI_TMSEL   5
#define EPI_ADDEX   6

// C[M, N] = A[M, K](lda) * B(^T).  K mult of 16, M mult of 64 (per batch).
// BKN=0: B is [N][K] row-major (ldb = row stride), N mult of 64  -> A*B^T
// BKN=1: B is [K][ldb] row-major, logical [K][N]; cols >= ldb read as 0 -> A*B
// blockIdx.z batches: A += z*sA, B += z*sB, C += z*sC.
template <int EPI, int BKN>
__global__ void __launch_bounds__(256) sgemm4_kernel(
        const float* __restrict__ A, int lda, long sA,
        const float* __restrict__ B, int ldb, long sB,
        float* __restrict__ Cm, int ldc, long sC, int N, int K,
        const float* __restrict__ bias,
        const unsigned char* __restrict__ mask,
        const float* __restrict__ token,
        const float* __restrict__ e1, const float* __restrict__ e2,
        const float* __restrict__ e3, const float* __restrict__ e4)
{
    A += (long)blockIdx.z * sA;
    B += (long)blockIdx.z * sB;
    Cm += (long)blockIdx.z * sC;
    __shared__ float As[2][16][64];
    __shared__ float Bs[2][16][64];
    int tid = threadIdx.x;            // 256
    int bm = blockIdx.y * 64;
    int bn = blockIdx.x * 64;
    int tx = (tid & 15) * 4;
    int ty = (tid >> 4) * 4;
    int lrow = tid >> 2, lkq = (tid & 3) * 4;
    int bkk = tid >> 4, bnn = (tid & 15) * 4;   // BKN=1 B-tile load
    float acc[4][4] = {};
    float4 ra, rb;

    // prologue: tile 0 -> buffer 0
    ra = *(const float4*)&A[(size_t)(bm + lrow) * lda + lkq];
    if (BKN) {
        rb = make_float4(0.f, 0.f, 0.f, 0.f);
        if (bn + bnn < ldb) rb = *(const float4*)&B[(size_t)bkk * ldb + bn + bnn];
    } else {
        rb = *(const float4*)&B[(size_t)(bn + lrow) * ldb + lkq];
    }
    As[0][lkq + 0][lrow] = ra.x; As[0][lkq + 1][lrow] = ra.y;
    As[0][lkq + 2][lrow] = ra.z; As[0][lkq + 3][lrow] = ra.w;
    if (BKN) {
        *(float4*)&Bs[0][bkk][bnn] = rb;
    } else {
        Bs[0][lkq + 0][lrow] = rb.x; Bs[0][lkq + 1][lrow] = rb.y;
        Bs[0][lkq + 2][lrow] = rb.z; Bs[0][lkq + 3][lrow] = rb.w;
    }
    __syncthreads();

    int p = 0;
    for (int k0 = 16; ; k0 += 16) {
        bool has_next = (k0 < K);
        if (has_next) {     // prefetch next tile into registers (hidden by compute)
            ra = *(const float4*)&A[(size_t)(bm + lrow) * lda + k0 + lkq];
            if (BKN) {
                rb = make_float4(0.f, 0.f, 0.f, 0.f);
                if (bn + bnn < ldb)
                    rb = *(const float4*)&B[(size_t)(k0 + bkk) * ldb + bn + bnn];
            } else {
                rb = *(const float4*)&B[(size_t)(bn + lrow) * ldb + k0 + lkq];
            }
        }
        #pragma unroll
        for (int kk = 0; kk < 16; kk++) {
            float4 a = *(const float4*)&As[p][kk][ty];
            float4 b = *(const float4*)&Bs[p][kk][tx];
            float am[4] = {a.x, a.y, a.z, a.w};
            float bv[4] = {b.x, b.y, b.z, b.w};
            #pragma unroll
            for (int i = 0; i < 4; i++)
                #pragma unroll
                for (int j = 0; j < 4; j++)
                    acc[i][j] = fmaf(am[i], bv[j], acc[i][j]);
        }
        if (!has_next) break;
        int q = p ^ 1;      // buffer q last read 2 iters ago; sync then guarantees free
        As[q][lkq + 0][lrow] = ra.x; As[q][lkq + 1][lrow] = ra.y;
        As[q][lkq + 2][lrow] = ra.z; As[q][lkq + 3][lrow] = ra.w;
        if (BKN) {
            *(float4*)&Bs[q][bkk][bnn] = rb;
        } else {
            Bs[q][lkq + 0][lrow] = rb.x; Bs[q][lkq + 1][lrow] = rb.y;
            Bs[q][lkq + 2][lrow] = rb.z; Bs[q][lkq + 3][lrow] = rb.w;
        }
        __syncthreads();
        p = q;
    }

    const bool vec = ((N & 3) == 0);
    #pragma unroll
    for (int i = 0; i < 4; i++) {
        int row = bm + ty + i;
        float v4[4];
        #pragma unroll
        for (int j = 0; j < 4; j++) {
            int col = bn + tx + j;
            float v = acc[i][j];
            if (EPI == EPI_PE) {
                v += bias[col];
                v += g_pe[(row & (T_ - 1)) * D_ + col];
            } else if (EPI == EPI_GELU) {
                v += bias[col];
                v = 0.5f * v * (1.f + erff(v * 0.70710678118654752f));
            } else if (EPI == EPI_SIGMASK) {
                v += bias[col];
                v = 1.f / (1.f + expf(-v));
                if (mask[row]) v = token[col];
            } else if (EPI == EPI_TMSEL) {
                if (!mask[row]) {
                    float m = v, a = 0.f;
                    for (int dd = 0; dd < D_; dd++) {
                        float u = fmaf(m, e1[dd], e2[dd]);
                        float g = 0.5f * u * (1.f + erff(u * 0.70710678118654752f));
                        a = fmaf(g, e3[dd], a);
                    }
                    v = 1.f / (1.f + expf(-(a + e4[0])));
                }
            } else if (EPI == EPI_ADDEX) {
                // mtd = ex + Wsub@delta  (irfft(rfft(ex)) == ex + masked delta)
                v += g_ex[((long)blockIdx.z * T_ + row) * D_ + col];
            }
            v4[j] = v;
        }
        if (vec) {
            *(float4*)&Cm[(size_t)row * ldc + bn + tx] =
                make_float4(v4[0], v4[1], v4[2], v4[3]);
        } else {
            #pragma unroll
            for (int j = 0; j < 4; j++) {
                int col = bn + tx + j;
                if (col < N) Cm[(size_t)row * ldc + col] = v4[j];
            }
        }
    }
}

// ---------------- windowed-variance score: one block per (b,t) -----------------
__global__ void score_kernel() {
    int bt = blockIdx.x;
    int b = bt >> 9, t = bt & 511;
    int tid = threadIdx.x;            // 256
    int t0 = t - (WIN_ - 1); if (t0 < 0) t0 = 0;
    float denom = (float)((t + 1 < WIN_) ? (t + 1) : WIN_);
    float num = 0.f, den = 0.f;
    for (int d = tid; d < D_; d += 256) {
        float s1 = 0.f, s2 = 0.f;
        const float* p = &g_ex[((size_t)b * T_ + t0) * D_ + d];
        for (int tt = t0; tt <= t; tt++) {
            float v = *p; p += D_;
            s1 += v;
            s2 = fmaf(v, v, s2);
        }
        float m1 = s1 / denom;
        num += s2 / denom - m1 * m1;
        den += m1;
    }
    __shared__ float sn[256], sd[256];
    sn[tid] = num; sd[tid] = den; __syncthreads();
    for (int s = 128; s > 0; s >>= 1) {
        if (tid < s) { sn[tid] += sn[tid + s]; sd[tid] += sd[tid + s]; }
        __syncthreads();
    }
    if (tid == 0) g_score[bt] = sn[0] / (sd[0] + 1e-6f);
}

// ---------------- top-k via rank selection (lax.top_k stable-desc semantics) ---
__global__ void topk_kernel(const float* __restrict__ vals, int n, int k,
                            int* __restrict__ idx_out,
                            unsigned char* __restrict__ mask_out,
                            float* __restrict__ outf)
{
    int b = blockIdx.x;
    int tid = threadIdx.x;            // 512
    __shared__ float v[512];
    for (int i = tid; i < n; i += blockDim.x) v[i] = vals[b * n + i];
    if (tid < n) mask_out[b * n + tid] = 0;
    __syncthreads();
    if (tid < n) {
        float x = v[tid];
        int rank = 0;
        for (int j = 0; j < n; j++) {
            float y = v[j];
            rank += (y > x) || (y == x && j < tid);
        }
        if (rank < k) {
            idx_out[b * k + rank] = tid;
            outf[b * k + rank] = (float)tid;
            mask_out[b * n + tid] = 1;
        }
    }
}

// ---------------- magnitude mean over d: one block per (b,f) -------------------
__global__ void mag_kernel() {
    int bf = blockIdx.x;
    int b = bf / F_, f = bf % F_;
    int d = threadIdx.x;              // 512
    float cr = g_cf[((size_t)b * MR + f) * D_ + d];
    float ci = (f == 0 || f == 256) ? 0.f
             : g_cf[((size_t)b * MR + 256 + f) * D_ + d];
    float m = sqrtf(cr * cr + ci * ci);
    __shared__ float red[512];
    red[d] = m; __syncthreads();
    for (int s = 256; s > 0; s >>= 1) {
        if (d < s) red[d] += red[d + s];
        __syncthreads();
    }
    if (d == 0) g_mag[bf] = red[0] * (1.f / 512.f);
}

// ---------------- time-domain mask tm = irfft(fmask) != 0 ----------------------
__global__ void tm_kernel() {
    int b = blockIdx.x;
    int t = threadIdx.x;              // 512
    const unsigned char* fm = &g_fmask[b * F_];
    float y = fm[0] ? 1.f : 0.f;
    for (int f = 1; f < 256; f++)
        if (fm[f]) y += 2.f * g_costab[(f * t) & 511];
    if (fm[256]) y += (t & 1) ? -1.f : 1.f;
    g_tm[b * T_ + t] = (y != 0.f) ? 1 : 0;
}

// ---------------- compact list of masked packed rows ---------------------------
__global__ void rowlist_kernel() {
    int b = blockIdx.x;
    int f = threadIdx.x;              // 512
    if (f < NDELTA) g_rowlist[b * NDELTA + f] = -1;
    __syncthreads();
    if (f < F_ && g_fmask[b * F_ + f]) {
        int rank = 0;
        for (int g2 = 0; g2 < f; g2++)
            if (g_fmask[b * F_ + g2]) rank += (g2 == 0 || g2 == 256) ? 1 : 2;
        g_rowlist[b * NDELTA + rank] = f;              // re row (packed index f)
        if (f >= 1 && f <= 255)
            g_rowlist[b * NDELTA + rank + 1] = 256 + f; // im row
    }
}

// ---------------- build delta (token - cf, masked rows) + gathered Widft cols --
__global__ void builddw_kernel(const float* __restrict__ f_tok_re,
                               const float* __restrict__ f_tok_im) {
    int i = blockIdx.x * blockDim.x + threadIdx.x;
    const int nD = B_ * NDELTA * D_;
    if (i < nD) {
        int b = i / (NDELTA * D_);
        int rem = i - b * NDELTA * D_;
        int j = rem >> 9, d = rem & 511;
        int r = g_rowlist[b * NDELTA + j];
        float v = 0.f;
        if (r >= 0) {
            float tok = (r <= 256) ? f_tok_re[d] : f_tok_im[d];
            v = tok - g_cf[((size_t)b * MR + r) * D_ + d];
        }
        g_delta[i] = v;
    } else {
        int k = i - nD;
        if (k < B_ * T_ * NDELTA) {
            int b = k / (T_ * NDELTA);
            int rem = k - b * T_ * NDELTA;
            int t = rem / NDELTA, j = rem % NDELTA;
            int r = g_rowlist[b * NDELTA + j];
            g_wsub[k] = (r >= 0) ? g_widft[t * KI + r] : 0.f;
        }
    }
}

// ---------------- launch ----------------
extern "C" void kernel_launch(void* const* d_in, const int* in_sizes, int n_in,
                              void* d_out, int out_size) {
    const float* x        = (const float*)d_in[0];
    const float* W_emb    = (const float*)d_in[1];
    const float* b_emb    = (const float*)d_in[2];
    const float* t_token  = (const float*)d_in[3];
    const float* tW1      = (const float*)d_in[4];
    const float* tb1      = (const float*)d_in[5];
    const float* tW2      = (const float*)d_in[6];
    const float* tb2      = (const float*)d_in[7];
    const float* f_tok_re = (const float*)d_in[8];
    const float* f_tok_im = (const float*)d_in[9];
    const float* fW1      = (const float*)d_in[10];
    const float* fb1      = (const float*)d_in[11];
    const float* fW2      = (const float*)d_in[12];
    const float* fb2      = (const float*)d_in[13];
    float* out = (float*)d_out;

    // output packing: out_t [B,T,D] | tidx [B,51] | out_f [B,T,C] | fidx [B,51]
    float* out_t    = out;
    float* out_tidx = out + (size_t)B_ * T_ * D_;
    float* out_f    = out_tidx + B_ * K_TOP;
    float* out_fidx = out_f + (size_t)B_ * T_ * C_;

    float *p_ex, *p_h, *p_mtd, *p_score, *p_mag, *p_xpad, *p_wpad;
    float *p_wdft, *p_widft, *p_cf, *p_delta, *p_wsub;
    int *p_tidx, *p_fidx;
    unsigned char *p_tmask, *p_fmask, *p_tm;
    cudaGetSymbolAddress((void**)&p_ex,    g_ex);
    cudaGetSymbolAddress((void**)&p_h,     g_h);
    cudaGetSymbolAddress((void**)&p_mtd,   g_mtd);
    cudaGetSymbolAddress((void**)&p_score, g_score);
    cudaGetSymbolAddress((void**)&p_mag,   g_mag);
    cudaGetSymbolAddress((void**)&p_xpad,  g_xpad);
    cudaGetSymbolAddress((void**)&p_wpad,  g_wpad);
    cudaGetSymbolAddress((void**)&p_wdft,  g_wdft);
    cudaGetSymbolAddress((void**)&p_widft, g_widft);
    cudaGetSymbolAddress((void**)&p_cf,    g_cf);
    cudaGetSymbolAddress((void**)&p_delta, g_delta);
    cudaGetSymbolAddress((void**)&p_wsub,  g_wsub);
    cudaGetSymbolAddress((void**)&p_tidx,  g_tidx);
    cudaGetSymbolAddress((void**)&p_fidx,  g_fidx);
    cudaGetSymbolAddress((void**)&p_tmask, g_tmask);
    cudaGetSymbolAddress((void**)&p_fmask, g_fmask);
    cudaGetSymbolAddress((void**)&p_tm,    g_tm);

    if (!g_sB) {
        cudaStreamCreateWithFlags(&g_sB, cudaStreamNonBlocking);
        cudaEventCreateWithFlags(&g_evStart, cudaEventDisableTiming);
        cudaEventCreateWithFlags(&g_evFork, cudaEventDisableTiming);
        cudaEventCreateWithFlags(&g_evJoin, cudaEventDisableTiming);
    }

    // ---- legal capture fork at t=0: g_sB joins the capture via evStart ----
    cudaEventRecord(g_evStart, 0);
    cudaStreamWaitEvent(g_sB, g_evStart, 0);

    // DFT weight tables on g_sB (input-independent; overlaps prologue + GEMM1)
    init_wdft_kernel<<<(MR * T_ + T_ * KI + 255) / 256, 256, 0, g_sB>>>();

    // ---- prologue on stream 0 ----
    init_div_kernel<<<1, 512>>>();
    prep_kernel<<<(T_ * D_ + (B_ * T_ + D_) * KPAD + 255) / 256, 256>>>(x, W_emb);

    // ex = x * W_emb^T + b_emb + PE      (padded K=272)
    sgemm4_kernel<EPI_PE, 0><<<dim3(D_ / 64, B_ * T_ / 64), 256>>>(
        p_xpad, KPAD, 0, p_wpad, KPAD, 0, p_ex, D_, 0, D_, KPAD,
        b_emb, nullptr, nullptr, nullptr, nullptr, nullptr, nullptr);

    // ---- fork: path B (frequency) continues on g_sB after ex is ready ----
    cudaEventRecord(g_evFork, 0);
    cudaStreamWaitEvent(g_sB, g_evFork, 0);
    {
        // cf[b] = Wdft[512,512] @ ex[b][512,512]   (packed re/im rows)
        sgemm4_kernel<EPI_NONE, 1><<<dim3(D_ / 64, MR / 64, B_), 256, 0, g_sB>>>(
            p_wdft, T_, 0, p_ex, D_, (long)T_ * D_, p_cf, D_, (long)MR * D_, D_, T_,
            nullptr, nullptr, nullptr, nullptr, nullptr, nullptr, nullptr);
        mag_kernel<<<B_ * F_, 512, 0, g_sB>>>();
        topk_kernel<<<B_, 512, 0, g_sB>>>(p_mag, F_, K_TOP, p_fidx, p_fmask, out_fidx);
        tm_kernel<<<B_, 512, 0, g_sB>>>();
        rowlist_kernel<<<B_, 512, 0, g_sB>>>();
        builddw_kernel<<<(B_ * NDELTA * D_ + B_ * T_ * NDELTA + 255) / 256, 256, 0, g_sB>>>(
            f_tok_re, f_tok_im);
        // mtd[b] = ex[b] + Wsub[b][512,112] @ delta[b][112,512]
        sgemm4_kernel<EPI_ADDEX, 1><<<dim3(D_ / 64, T_ / 64, B_), 256, 0, g_sB>>>(
            p_wsub, NDELTA, (long)T_ * NDELTA,
            p_delta, D_, (long)NDELTA * D_,
            p_mtd, D_, (long)T_ * D_, D_, NDELTA,
            nullptr, nullptr, nullptr, nullptr, nullptr, nullptr, nullptr);
        // out_f = tmsel(mtd @ W_emb)   (fused mx + outf)
        sgemm4_kernel<EPI_TMSEL, 1><<<dim3((C_ + 63) / 64, B_ * T_ / 64), 256, 0, g_sB>>>(
            p_mtd, D_, 0, p_wpad, KPAD, 0, out_f, C_, 0, C_, D_,
            nullptr, p_tm, nullptr, fW1, fb1, fW2, fb2);
        cudaEventRecord(g_evJoin, g_sB);
    }

    // ---- path A (temporal) on stream 0 ----
    score_kernel<<<B_ * T_, 256>>>();
    topk_kernel<<<B_, 512>>>(p_score, T_, K_TOP, p_tidx, p_tmask, out_tidx);
    // h = gelu(ex * tW1^T + tb1)
    sgemm4_kernel<EPI_GELU, 0><<<dim3(D_ / 64, B_ * T_ / 64), 256>>>(
        p_ex, D_, 0, tW1, D_, 0, p_h, D_, 0, D_, D_,
        tb1, nullptr, nullptr, nullptr, nullptr, nullptr, nullptr);
    // out_t = tmask ? t_token : sigmoid(h * tW2^T + tb2)
    sgemm4_kernel<EPI_SIGMASK, 0><<<dim3(D_ / 64, B_ * T_ / 64), 256>>>(
        p_h, D_, 0, tW2, D_, 0, out_t, D_, 0, D_, D_,
        tb2, p_tmask, t_token, nullptr, nullptr, nullptr, nullptr);

    // ---- join ----
    cudaStreamWaitEvent(0, g_evJoin, 0);
}

// round 9
// speedup vs baseline: 1.8623x; 1.1526x over previous
#include <cuda_runtime.h>
#include <math.h>

#define B_ 2
#define T_ 512
#define C_ 263
#define D_ 512
#define F_ 257          // T/2 + 1
#define K_TOP 51        // int(512 * 0.1)
#define WIN_ 24
#define KPAD 288        // 263 padded to multiple of 32 (zero-filled)

// packed spectrum: row f in [0,256] = re_f ; row 256+f for f in [1,255] = im_f
#define MR 512
#define KI 512
#define NDELTA 128      // max masked packed rows (<=102), padded to mult of 32

// ---------------- scratch (static device memory; no allocation) ----------------
__device__ float g_ex [B_*T_*D_];
__device__ float g_h  [B_*T_*D_];
__device__ float g_mtd[B_*T_*D_];
__device__ float g_cf [B_*MR*D_];
__device__ float g_delta[B_*NDELTA*D_];     // (token - cf) at masked packed rows
__device__ float g_wsub [B_*T_*NDELTA];     // gathered Widft columns
__device__ int   g_rowlist[B_*NDELTA];
__device__ float g_score[B_*T_];
__device__ float g_mag  [B_*F_];
__device__ int   g_tidx[B_*K_TOP];
__device__ int   g_fidx[B_*K_TOP];
__device__ unsigned char g_tmask[B_*T_];
__device__ unsigned char g_fmask[B_*F_];
__device__ unsigned char g_tm   [B_*T_];
__device__ float g_costab[512];
__device__ float g_sintab[512];
__device__ float g_pe[T_*D_];
__device__ double g_div[256];
__device__ float g_xpad[B_*T_*KPAD + 64];
__device__ float g_wpad[D_*KPAD + 64];
__device__ float g_wdft [MR*T_];
__device__ float g_widft[T_*KI];

// ---------------- streams/events (created in static ctor, pre-checkpoint) ------
static cudaStream_t g_sB = nullptr, g_sC = nullptr;
static cudaEvent_t g_evStart = nullptr, g_evFork = nullptr;
static cudaEvent_t g_evJoin = nullptr, g_evC = nullptr;
namespace {
struct StreamInit {
    StreamInit() {
        cudaStreamCreateWithFlags(&g_sB, cudaStreamNonBlocking);
        cudaStreamCreateWithFlags(&g_sC, cudaStreamNonBlocking);
        cudaEventCreateWithFlags(&g_evStart, cudaEventDisableTiming);
        cudaEventCreateWithFlags(&g_evFork, cudaEventDisableTiming);
        cudaEventCreateWithFlags(&g_evJoin, cudaEventDisableTiming);
        cudaEventCreateWithFlags(&g_evC, cudaEventDisableTiming);
    }
};
StreamInit g_streamInit;
}

// ---------------- table init ----------------------------------------------------
__global__ void init_div_kernel() {
    int i = threadIdx.x;
    if (i < 256) {
        g_div[i] = exp(-(double)(2 * i) * (9.210340371976184 / 512.0));
    }
    if (i < 512) {
        float s, c;
        sincospif((float)i / 256.0f, &s, &c);
        g_costab[i] = c; g_sintab[i] = s;
    }
}

// merged: PE table + pad x -> [B*T][288] + pad W_emb -> [D][288]
__global__ void prep_kernel(const float* __restrict__ x, const float* __restrict__ w) {
    int i = blockIdx.x * blockDim.x + threadIdx.x;
    const int nPE = T_ * D_;
    const int nX  = B_ * T_ * KPAD;
    if (i < nPE) {
        int t = i / D_, d = i % D_;
        double arg = (double)t * g_div[d >> 1];
        const double PI2 = 6.283185307179586476925286766559;
        double q = rint(arg * (1.0 / PI2));
        float rf = (float)(arg - q * PI2);
        g_pe[i] = (d & 1) ? cosf(rf) : sinf(rf);
    } else if (i < nPE + nX) {
        int j = i - nPE;
        int r = j / KPAD, c = j % KPAD;
        g_xpad[j] = (c < C_) ? x[r * C_ + c] : 0.f;
    } else {
        int j = i - nPE - nX;
        if (j < D_ * KPAD) {
            int r = j / KPAD, c = j % KPAD;
            g_wpad[j] = (c < C_) ? w[r * C_ + c] : 0.f;
        }
    }
}

// DFT weight tables (input-independent; identical twiddle values)
__global__ void init_wdft_kernel() {
    int i = blockIdx.x * blockDim.x + threadIdx.x;
    const int n1 = MR * T_;
    if (i < n1) {
        int r = i >> 9, t = i & 511;
        float s, c;
        if (r <= 256) {
            sincospif((float)((r * t) & 511) / 256.0f, &s, &c);
            g_wdft[i] = c;
        } else {
            sincospif((float)(((r - 256) * t) & 511) / 256.0f, &s, &c);
            g_wdft[i] = -s;
        }
    } else {
        int j = i - n1;
        if (j < T_ * KI) {
            int t = j >> 9, c = j & 511;
            float s, cc;
            if (c <= 256) {
                float w = (c == 0 || c == 256) ? (1.f / 512.f) : (2.f / 512.f);
                sincospif((float)((c * t) & 511) / 256.0f, &s, &cc);
                g_widft[j] = w * cc;
            } else {
                int f = c - 256;
                sincospif((float)((f * t) & 511) / 256.0f, &s, &cc);
                g_widft[j] = -(2.f / 512.f) * s;
            }
        }
    }
}

// ---------------- SGEMM v5: 64x64x32, 256 thr (1 blk/SM), double-buffered ------
#define EPI_NONE    0
#define EPI_PE      2
#define EPI_GELU    3
#define EPI_SIGMASK 4
#define EPI_TMSEL   5
#define EPI_ADDEX   6

// C[M, N] = A[M, K](lda) * B(^T).  K mult of 32, M mult of 64 (per batch).
// BKN=0: B is [N][K] row-major (ldb = row stride), N mult of 64  -> A*B^T
// BKN=1: B is [K][ldb] row-major, logical [K][N]; cols >= ldb read as 0 -> A*B
// blockIdx.z batches: A += z*sA, B += z*sB, C += z*sC.
template <int EPI, int BKN>
__global__ void __launch_bounds__(256, 1) sgemm5_kernel(
        const float* __restrict__ A, int lda, long sA,
        const float* __restrict__ B, int ldb, long sB,
        float* __restrict__ Cm, int ldc, long sC, int N, int K,
        const float* __restrict__ bias,
        const unsigned char* __restrict__ mask,
        const float* __restrict__ token,
        const float* __restrict__ e1, const float* __restrict__ e2,
        const float* __restrict__ e3, const float* __restrict__ e4)
{
    A += (long)blockIdx.z * sA;
    B += (long)blockIdx.z * sB;
    Cm += (long)blockIdx.z * sC;
    __shared__ float As[2][32][64];
    __shared__ float Bs[2][32][64];
    int tid = threadIdx.x;            // 256
    int bm = blockIdx.y * 64;
    int bn = blockIdx.x * 64;
    int tx = (tid & 15) * 4;
    int ty = (tid >> 4) * 4;
    int lrow = tid >> 2, lkq = (tid & 3) * 4;   // A / B^T loads (k 0..15, +16)
    int bkk = tid >> 4, bnn = (tid & 15) * 4;   // BKN=1 B loads (k rows, +16)
    float acc[4][4] = {};
    float4 ra0, ra1, rb0, rb1;

    // prologue: tile 0 -> buffer 0
    ra0 = *(const float4*)&A[(size_t)(bm + lrow) * lda + lkq];
    ra1 = *(const float4*)&A[(size_t)(bm + lrow) * lda + lkq + 16];
    if (BKN) {
        rb0 = make_float4(0.f, 0.f, 0.f, 0.f);
        rb1 = rb0;
        if (bn + bnn < ldb) {
            rb0 = *(const float4*)&B[(size_t)bkk * ldb + bn + bnn];
            rb1 = *(const float4*)&B[(size_t)(bkk + 16) * ldb + bn + bnn];
        }
    } else {
        rb0 = *(const float4*)&B[(size_t)(bn + lrow) * ldb + lkq];
        rb1 = *(const float4*)&B[(size_t)(bn + lrow) * ldb + lkq + 16];
    }
    As[0][lkq + 0][lrow] = ra0.x; As[0][lkq + 1][lrow] = ra0.y;
    As[0][lkq + 2][lrow] = ra0.z; As[0][lkq + 3][lrow] = ra0.w;
    As[0][lkq + 16][lrow] = ra1.x; As[0][lkq + 17][lrow] = ra1.y;
    As[0][lkq + 18][lrow] = ra1.z; As[0][lkq + 19][lrow] = ra1.w;
    if (BKN) {
        *(float4*)&Bs[0][bkk][bnn] = rb0;
        *(float4*)&Bs[0][bkk + 16][bnn] = rb1;
    } else {
        Bs[0][lkq + 0][lrow] = rb0.x; Bs[0][lkq + 1][lrow] = rb0.y;
        Bs[0][lkq + 2][lrow] = rb0.z; Bs[0][lkq + 3][lrow] = rb0.w;
        Bs[0][lkq + 16][lrow] = rb1.x; Bs[0][lkq + 17][lrow] = rb1.y;
        Bs[0][lkq + 18][lrow] = rb1.z; Bs[0][lkq + 19][lrow] = rb1.w;
    }
    __syncthreads();

    int p = 0;
    for (int k0 = 32; ; k0 += 32) {
        bool has_next = (k0 < K);
        if (has_next) {     // prefetch next tile into registers (hidden by compute)
            ra0 = *(const float4*)&A[(size_t)(bm + lrow) * lda + k0 + lkq];
            ra1 = *(const float4*)&A[(size_t)(bm + lrow) * lda + k0 + lkq + 16];
            if (BKN) {
                rb0 = make_float4(0.f, 0.f, 0.f, 0.f);
                rb1 = rb0;
                if (bn + bnn < ldb) {
                    rb0 = *(const float4*)&B[(size_t)(k0 + bkk) * ldb + bn + bnn];
                    rb1 = *(const float4*)&B[(size_t)(k0 + bkk + 16) * ldb + bn + bnn];
                }
            } else {
                rb0 = *(const float4*)&B[(size_t)(bn + lrow) * ldb + k0 + lkq];
                rb1 = *(const float4*)&B[(size_t)(bn + lrow) * ldb + k0 + lkq + 16];
            }
        }
        #pragma unroll
        for (int kk = 0; kk < 32; kk++) {
            float4 a = *(const float4*)&As[p][kk][ty];
            float4 b = *(const float4*)&Bs[p][kk][tx];
            float am[4] = {a.x, a.y, a.z, a.w};
            float bv[4] = {b.x, b.y, b.z, b.w};
            #pragma unroll
            for (int i = 0; i < 4; i++)
                #pragma unroll
                for (int j = 0; j < 4; j++)
                    acc[i][j] = fmaf(am[i], bv[j], acc[i][j]);
        }
        if (!has_next) break;
        int q = p ^ 1;
        As[q][lkq + 0][lrow] = ra0.x; As[q][lkq + 1][lrow] = ra0.y;
        As[q][lkq + 2][lrow] = ra0.z; As[q][lkq + 3][lrow] = ra0.w;
        As[q][lkq + 16][lrow] = ra1.x; As[q][lkq + 17][lrow] = ra1.y;
        As[q][lkq + 18][lrow] = ra1.z; As[q][lkq + 19][lrow] = ra1.w;
        if (BKN) {
            *(float4*)&Bs[q][bkk][bnn] = rb0;
            *(float4*)&Bs[q][bkk + 16][bnn] = rb1;
        } else {
            Bs[q][lkq + 0][lrow] = rb0.x; Bs[q][lkq + 1][lrow] = rb0.y;
            Bs[q][lkq + 2][lrow] = rb0.z; Bs[q][lkq + 3][lrow] = rb0.w;
            Bs[q][lkq + 16][lrow] = rb1.x; Bs[q][lkq + 17][lrow] = rb1.y;
            Bs[q][lkq + 18][lrow] = rb1.z; Bs[q][lkq + 19][lrow] = rb1.w;
        }
        __syncthreads();
        p = q;
    }

    const bool vec = ((N & 3) == 0);
    #pragma unroll
    for (int i = 0; i < 4; i++) {
        int row = bm + ty + i;
        float v4[4];
        #pragma unroll
        for (int j = 0; j < 4; j++) {
            int col = bn + tx + j;
            float v = acc[i][j];
            if (EPI == EPI_PE) {
                v += bias[col];
                v += g_pe[(row & (T_ - 1)) * D_ + col];
            } else if (EPI == EPI_GELU) {
                v += bias[col];
                v = 0.5f * v * (1.f + erff(v * 0.70710678118654752f));
            } else if (EPI == EPI_SIGMASK) {
                v += bias[col];
                v = 1.f / (1.f + expf(-v));
                if (mask[row]) v = token[col];
            } else if (EPI == EPI_TMSEL) {
                if (!mask[row]) {
                    float m = v, a = 0.f;
                    for (int dd = 0; dd < D_; dd++) {
                        float u = fmaf(m, e1[dd], e2[dd]);
                        float g = 0.5f * u * (1.f + erff(u * 0.70710678118654752f));
                        a = fmaf(g, e3[dd], a);
                    }
                    v = 1.f / (1.f + expf(-(a + e4[0])));
                }
            } else if (EPI == EPI_ADDEX) {
                // mtd = ex + Wsub@delta  (irfft(rfft(ex)) == ex + masked delta)
                v += g_ex[((long)blockIdx.z * T_ + row) * D_ + col];
            }
            v4[j] = v;
        }
        if (vec) {
            *(float4*)&Cm[(size_t)row * ldc + bn + tx] =
                make_float4(v4[0], v4[1], v4[2], v4[3]);
        } else {
            #pragma unroll
            for (int j = 0; j < 4; j++) {
                int col = bn + tx + j;
                if (col < N) Cm[(size_t)row * ldc + col] = v4[j];
            }
        }
    }
}

// ---------------- windowed-variance score: one block per (b,t) -----------------
__global__ void score_kernel() {
    int bt = blockIdx.x;
    int b = bt >> 9, t = bt & 511;
    int tid = threadIdx.x;            // 256
    int t0 = t - (WIN_ - 1); if (t0 < 0) t0 = 0;
    float denom = (float)((t + 1 < WIN_) ? (t + 1) : WIN_);
    float num = 0.f, den = 0.f;
    for (int d = tid; d < D_; d += 256) {
        float s1 = 0.f, s2 = 0.f;
        const float* p = &g_ex[((size_t)b * T_ + t0) * D_ + d];
        for (int tt = t0; tt <= t; tt++) {
            float v = *p; p += D_;
            s1 += v;
            s2 = fmaf(v, v, s2);
        }
        float m1 = s1 / denom;
        num += s2 / denom - m1 * m1;
        den += m1;
    }
    __shared__ float sn[256], sd[256];
    sn[tid] = num; sd[tid] = den; __syncthreads();
    for (int s = 128; s > 0; s >>= 1) {
        if (tid < s) { sn[tid] += sn[tid + s]; sd[tid] += sd[tid + s]; }
        __syncthreads();
    }
    if (tid == 0) g_score[bt] = sn[0] / (sd[0] + 1e-6f);
}

// ---------------- top-k via rank selection (lax.top_k stable-desc semantics) ---
__global__ void topk_kernel(const float* __restrict__ vals, int n, int k,
                            int* __restrict__ idx_out,
                            unsigned char* __restrict__ mask_out,
                            float* __restrict__ outf)
{
    int b = blockIdx.x;
    int tid = threadIdx.x;            // 512
    __shared__ float v[512];
    for (int i = tid; i < n; i += blockDim.x) v[i] = vals[b * n + i];
    if (tid < n) mask_out[b * n + tid] = 0;
    __syncthreads();
    if (tid < n) {
        float x = v[tid];
        int rank = 0;
        for (int j = 0; j < n; j++) {
            float y = v[j];
            rank += (y > x) || (y == x && j < tid);
        }
        if (rank < k) {
            idx_out[b * k + rank] = tid;
            outf[b * k + rank] = (float)tid;
            mask_out[b * n + tid] = 1;
        }
    }
}

// ---------------- magnitude mean over d: one block per (b,f) -------------------
__global__ void mag_kernel() {
    int bf = blockIdx.x;
    int b = bf / F_, f = bf % F_;
    int d = threadIdx.x;              // 512
    float cr = g_cf[((size_t)b * MR + f) * D_ + d];
    float ci = (f == 0 || f == 256) ? 0.f
             : g_cf[((size_t)b * MR + 256 + f) * D_ + d];
    float m = sqrtf(cr * cr + ci * ci);
    __shared__ float red[512];
    red[d] = m; __syncthreads();
    for (int s = 256; s > 0; s >>= 1) {
        if (d < s) red[d] += red[d + s];
        __syncthreads();
    }
    if (d == 0) g_mag[bf] = red[0] * (1.f / 512.f);
}

// ---------------- merged: tm mask + compacted masked-row list ------------------
__global__ void tmrow_kernel() {
    int b = blockIdx.x;
    int tid = threadIdx.x;            // 512
    if (tid < NDELTA) g_rowlist[b * NDELTA + tid] = -1;
    __syncthreads();
    // tm = irfft(fmask) != 0   (t = tid)
    {
        const unsigned char* fm = &g_fmask[b * F_];
        int t = tid;
        float y = fm[0] ? 1.f : 0.f;
        for (int f = 1; f < 256; f++)
            if (fm[f]) y += 2.f * g_costab[(f * t) & 511];
        if (fm[256]) y += (t & 1) ? -1.f : 1.f;
        g_tm[b * T_ + t] = (y != 0.f) ? 1 : 0;
    }
    // rowlist scatter (f = tid)
    if (tid < F_ && g_fmask[b * F_ + tid]) {
        int f = tid;
        int rank = 0;
        for (int g2 = 0; g2 < f; g2++)
            if (g_fmask[b * F_ + g2]) rank += (g2 == 0 || g2 == 256) ? 1 : 2;
        g_rowlist[b * NDELTA + rank] = f;               // re row
        if (f >= 1 && f <= 255)
            g_rowlist[b * NDELTA + rank + 1] = 256 + f; // im row
    }
}

// ---------------- build delta (token - cf, masked rows) + gathered Widft cols --
__global__ void builddw_kernel(const float* __restrict__ f_tok_re,
                               const float* __restrict__ f_tok_im) {
    int i = blockIdx.x * blockDim.x + threadIdx.x;
    const int nD = B_ * NDELTA * D_;
    if (i < nD) {
        int b = i / (NDELTA * D_);
        int rem = i - b * NDELTA * D_;
        int j = rem >> 9, d = rem & 511;
        int r = g_rowlist[b * NDELTA + j];
        float v = 0.f;
        if (r >= 0) {
            float tok = (r <= 256) ? f_tok_re[d] : f_tok_im[d];
            v = tok - g_cf[((size_t)b * MR + r) * D_ + d];
        }
        g_delta[i] = v;
    } else {
        int k = i - nD;
        if (k < B_ * T_ * NDELTA) {
            int b = k / (T_ * NDELTA);
            int rem = k - b * T_ * NDELTA;
            int t = rem / NDELTA, j = rem % NDELTA;
            int r = g_rowlist[b * NDELTA + j];
            g_wsub[k] = (r >= 0) ? g_widft[t * KI + r] : 0.f;
        }
    }
}

// ---------------- launch ----------------
extern "C" void kernel_launch(void* const* d_in, const int* in_sizes, int n_in,
                              void* d_out, int out_size) {
    const float* x        = (const float*)d_in[0];
    const float* W_emb    = (const float*)d_in[1];
    const float* b_emb    = (const float*)d_in[2];
    const float* t_token  = (const float*)d_in[3];
    const float* tW1      = (const float*)d_in[4];
    const float* tb1      = (const float*)d_in[5];
    const float* tW2      = (const float*)d_in[6];
    const float* tb2      = (const float*)d_in[7];
    const float* f_tok_re = (const float*)d_in[8];
    const float* f_tok_im = (const float*)d_in[9];
    const float* fW1      = (const float*)d_in[10];
    const float* fb1      = (const float*)d_in[11];
    const float* fW2      = (const float*)d_in[12];
    const float* fb2      = (const float*)d_in[13];
    float* out = (float*)d_out;

    // output packing: out_t [B,T,D] | tidx [B,51] | out_f [B,T,C] | fidx [B,51]
    float* out_t    = out;
    float* out_tidx = out + (size_t)B_ * T_ * D_;
    float* out_f    = out_tidx + B_ * K_TOP;
    float* out_fidx = out_f + (size_t)B_ * T_ * C_;

    float *p_ex, *p_h, *p_mtd, *p_score, *p_mag, *p_xpad, *p_wpad;
    float *p_wdft, *p_widft, *p_cf, *p_delta, *p_wsub;
    int *p_tidx, *p_fidx;
    unsigned char *p_tmask, *p_fmask, *p_tm;
    cudaGetSymbolAddress((void**)&p_ex,    g_ex);
    cudaGetSymbolAddress((void**)&p_h,     g_h);
    cudaGetSymbolAddress((void**)&p_mtd,   g_mtd);
    cudaGetSymbolAddress((void**)&p_score, g_score);
    cudaGetSymbolAddress((void**)&p_mag,   g_mag);
    cudaGetSymbolAddress((void**)&p_xpad,  g_xpad);
    cudaGetSymbolAddress((void**)&p_wpad,  g_wpad);
    cudaGetSymbolAddress((void**)&p_wdft,  g_wdft);
    cudaGetSymbolAddress((void**)&p_widft, g_widft);
    cudaGetSymbolAddress((void**)&p_cf,    g_cf);
    cudaGetSymbolAddress((void**)&p_delta, g_delta);
    cudaGetSymbolAddress((void**)&p_wsub,  g_wsub);
    cudaGetSymbolAddress((void**)&p_tidx,  g_tidx);
    cudaGetSymbolAddress((void**)&p_fidx,  g_fidx);
    cudaGetSymbolAddress((void**)&p_tmask, g_tmask);
    cudaGetSymbolAddress((void**)&p_fmask, g_fmask);
    cudaGetSymbolAddress((void**)&p_tm,    g_tm);

    if (!g_sB) {
        cudaStreamCreateWithFlags(&g_sB, cudaStreamNonBlocking);
        cudaStreamCreateWithFlags(&g_sC, cudaStreamNonBlocking);
        cudaEventCreateWithFlags(&g_evStart, cudaEventDisableTiming);
        cudaEventCreateWithFlags(&g_evFork, cudaEventDisableTiming);
        cudaEventCreateWithFlags(&g_evJoin, cudaEventDisableTiming);
        cudaEventCreateWithFlags(&g_evC, cudaEventDisableTiming);
    }

    // ---- legal capture fork at t=0 ----
    cudaEventRecord(g_evStart, 0);
    cudaStreamWaitEvent(g_sB, g_evStart, 0);

    // DFT weight tables on g_sB (input-independent; overlaps prologue + GEMM1)
    init_wdft_kernel<<<(MR * T_ + T_ * KI + 255) / 256, 256, 0, g_sB>>>();

    // ---- prologue on stream 0 ----
    init_div_kernel<<<1, 512>>>();
    prep_kernel<<<(T_ * D_ + (B_ * T_ + D_) * KPAD + 255) / 256, 256>>>(x, W_emb);

    // ex = x * W_emb^T + b_emb + PE      (padded K=288)
    sgemm5_kernel<EPI_PE, 0><<<dim3(D_ / 64, B_ * T_ / 64), 256>>>(
        p_xpad, KPAD, 0, p_wpad, KPAD, 0, p_ex, D_, 0, D_, KPAD,
        b_emb, nullptr, nullptr, nullptr, nullptr, nullptr, nullptr);

    // ---- fork after ex ----
    cudaEventRecord(g_evFork, 0);
    cudaStreamWaitEvent(g_sB, g_evFork, 0);
    cudaStreamWaitEvent(g_sC, g_evFork, 0);

    // ---- path C: score + temporal top-k (overlaps h-GEMM) ----
    score_kernel<<<B_ * T_, 256, 0, g_sC>>>();
    topk_kernel<<<B_, 512, 0, g_sC>>>(p_score, T_, K_TOP, p_tidx, p_tmask, out_tidx);
    cudaEventRecord(g_evC, g_sC);

    // ---- path B (frequency) on g_sB ----
    {
        // cf[b] = Wdft[512,512] @ ex[b][512,512]   (packed re/im rows)
        sgemm5_kernel<EPI_NONE, 1><<<dim3(D_ / 64, MR / 64, B_), 256, 0, g_sB>>>(
            p_wdft, T_, 0, p_ex, D_, (long)T_ * D_, p_cf, D_, (long)MR * D_, D_, T_,
            nullptr, nullptr, nullptr, nullptr, nullptr, nullptr, nullptr);
        mag_kernel<<<B_ * F_, 512, 0, g_sB>>>();
        topk_kernel<<<B_, 512, 0, g_sB>>>(p_mag, F_, K_TOP, p_fidx, p_fmask, out_fidx);
        tmrow_kernel<<<B_, 512, 0, g_sB>>>();
        builddw_kernel<<<(B_ * NDELTA * D_ + B_ * T_ * NDELTA + 255) / 256, 256, 0, g_sB>>>(
            f_tok_re, f_tok_im);
        // mtd[b] = ex[b] + Wsub[b][512,128] @ delta[b][128,512]
        sgemm5_kernel<EPI_ADDEX, 1><<<dim3(D_ / 64, T_ / 64, B_), 256, 0, g_sB>>>(
            p_wsub, NDELTA, (long)T_ * NDELTA,
            p_delta, D_, (long)NDELTA * D_,
            p_mtd, D_, (long)T_ * D_, D_, NDELTA,
            nullptr, nullptr, nullptr, nullptr, nullptr, nullptr, nullptr);
        // out_f = tmsel(mtd @ W_emb)   (fused mx + outf)
        sgemm5_kernel<EPI_TMSEL, 1><<<dim3((C_ + 63) / 64, B_ * T_ / 64), 256, 0, g_sB>>>(
            p_mtd, D_, 0, p_wpad, KPAD, 0, out_f, C_, 0, C_, D_,
            nullptr, p_tm, nullptr, fW1, fb1, fW2, fb2);
        cudaEventRecord(g_evJoin, g_sB);
    }

    // ---- path A (temporal GEMMs) on stream 0 ----
    // h = gelu(ex * tW1^T + tb1)   — independent of score/topk
    sgemm5_kernel<EPI_GELU, 0><<<dim3(D_ / 64, B_ * T_ / 64), 256>>>(
        p_ex, D_, 0, tW1, D_, 0, p_h, D_, 0, D_, D_,
        tb1, nullptr, nullptr, nullptr, nullptr, nullptr, nullptr);
    // out_t = tmask ? t_token : sigmoid(h * tW2^T + tb2)  — needs tmask from path C
    cudaStreamWaitEvent(0, g_evC, 0);
    sgemm5_kernel<EPI_SIGMASK, 0><<<dim3(D_ / 64, B_ * T_ / 64), 256>>>(
        p_h, D_, 0, tW2, D_, 0, out_t, D_, 0, D_, D_,
        tb2, p_tmask, t_token, nullptr, nullptr, nullptr, nullptr);

    // ---- join ----
    cudaStreamWaitEvent(0, g_evJoin, 0);
}

// round 10
// speedup vs baseline: 1.9206x; 1.0313x over previous
#include <cuda_runtime.h>
#include <math.h>

#define B_ 2
#define T_ 512
#define C_ 263
#define D_ 512
#define F_ 257          // T/2 + 1
#define K_TOP 51        // int(512 * 0.1)
#define WIN_ 24
#define KPAD 288        // 263 padded to multiple of 32 (zero-filled)

// packed spectrum: row f in [0,256] = re_f ; row 256+f for f in [1,255] = im_f
#define MR 512
#define KI 512
#define NDELTA 128      // max masked packed rows (<=102), padded to mult of 32

// ---------------- scratch (static device memory; no allocation) ----------------
__device__ float g_ex [B_*T_*D_];
__device__ float g_h  [B_*T_*D_];
__device__ float g_mtd[B_*T_*D_];
__device__ float g_cf [B_*MR*D_];
__device__ float g_delta[B_*NDELTA*D_];     // (token - cf) at masked packed rows
__device__ float g_wsub [B_*T_*NDELTA];     // gathered Widft columns
__device__ int   g_rowlist[B_*NDELTA];
__device__ float g_score[B_*T_];
__device__ float g_mag  [B_*F_];
__device__ int   g_tidx[B_*K_TOP];
__device__ int   g_fidx[B_*K_TOP];
__device__ unsigned char g_tmask[B_*T_];
__device__ unsigned char g_fmask[B_*F_];
__device__ unsigned char g_tm   [B_*T_];
__device__ float g_costab[512];
__device__ float g_sintab[512];
__device__ float g_pe[T_*D_];
__device__ double g_div[256];
__device__ float g_xpad[B_*T_*KPAD + 64];
__device__ float g_wpad[D_*KPAD + 64];
__device__ float g_wdft [MR*T_];
__device__ float g_widft[T_*KI];

// ---------------- streams/events (created in static ctor, pre-checkpoint) ------
static cudaStream_t g_sB = nullptr, g_sC = nullptr;
static cudaEvent_t g_evStart = nullptr, g_evFork = nullptr;
static cudaEvent_t g_evJoin = nullptr, g_evC = nullptr;
namespace {
struct StreamInit {
    StreamInit() {
        cudaStreamCreateWithFlags(&g_sB, cudaStreamNonBlocking);
        cudaStreamCreateWithFlags(&g_sC, cudaStreamNonBlocking);
        cudaEventCreateWithFlags(&g_evStart, cudaEventDisableTiming);
        cudaEventCreateWithFlags(&g_evFork, cudaEventDisableTiming);
        cudaEventCreateWithFlags(&g_evJoin, cudaEventDisableTiming);
        cudaEventCreateWithFlags(&g_evC, cudaEventDisableTiming);
    }
};
StreamInit g_streamInit;
}

// ---------------- table init ----------------------------------------------------
__global__ void init_div_kernel() {
    int i = threadIdx.x;
    if (i < 256) {
        g_div[i] = exp(-(double)(2 * i) * (9.210340371976184 / 512.0));
    }
    if (i < 512) {
        float s, c;
        sincospif((float)i / 256.0f, &s, &c);
        g_costab[i] = c; g_sintab[i] = s;
    }
}

// merged: PE table + pad x -> [B*T][288] + pad W_emb -> [D][288]
__global__ void prep_kernel(const float* __restrict__ x, const float* __restrict__ w) {
    int i = blockIdx.x * blockDim.x + threadIdx.x;
    const int nPE = T_ * D_;
    const int nX  = B_ * T_ * KPAD;
    if (i < nPE) {
        int t = i / D_, d = i % D_;
        double arg = (double)t * g_div[d >> 1];
        const double PI2 = 6.283185307179586476925286766559;
        double q = rint(arg * (1.0 / PI2));
        float rf = (float)(arg - q * PI2);
        g_pe[i] = (d & 1) ? cosf(rf) : sinf(rf);
    } else if (i < nPE + nX) {
        int j = i - nPE;
        int r = j / KPAD, c = j % KPAD;
        g_xpad[j] = (c < C_) ? x[r * C_ + c] : 0.f;
    } else {
        int j = i - nPE - nX;
        if (j < D_ * KPAD) {
            int r = j / KPAD, c = j % KPAD;
            g_wpad[j] = (c < C_) ? w[r * C_ + c] : 0.f;
        }
    }
}

// DFT weight tables (input-independent; identical twiddle values)
__global__ void init_wdft_kernel() {
    int i = blockIdx.x * blockDim.x + threadIdx.x;
    const int n1 = MR * T_;
    if (i < n1) {
        int r = i >> 9, t = i & 511;
        float s, c;
        if (r <= 256) {
            sincospif((float)((r * t) & 511) / 256.0f, &s, &c);
            g_wdft[i] = c;
        } else {
            sincospif((float)(((r - 256) * t) & 511) / 256.0f, &s, &c);
            g_wdft[i] = -s;
        }
    } else {
        int j = i - n1;
        if (j < T_ * KI) {
            int t = j >> 9, c = j & 511;
            float s, cc;
            if (c <= 256) {
                float w = (c == 0 || c == 256) ? (1.f / 512.f) : (2.f / 512.f);
                sincospif((float)((c * t) & 511) / 256.0f, &s, &cc);
                g_widft[j] = w * cc;
            } else {
                int f = c - 256;
                sincospif((float)((f * t) & 511) / 256.0f, &s, &cc);
                g_widft[j] = -(2.f / 512.f) * s;
            }
        }
    }
}

// ---------------- SGEMM v6: 64m x 32n x 32k, 128 thr, 2 blk/SM, dbl-buffered ---
#define EPI_NONE    0
#define EPI_PE      2
#define EPI_GELU    3
#define EPI_SIGMASK 4
#define EPI_TMSEL   5
#define EPI_ADDEX   6

// C[M, N] = A[M, K](lda) * B(^T).  K mult of 32, M mult of 64 (per batch).
// BKN=0: B is [N][K] row-major (ldb = row stride), N mult of 32  -> A*B^T
// BKN=1: B is [K][ldb] row-major, logical [K][N]; cols >= ldb read as 0 -> A*B
// blockIdx.z batches: A += z*sA, B += z*sB, C += z*sC.
template <int EPI, int BKN>
__global__ void __launch_bounds__(128, 2) sgemm6_kernel(
        const float* __restrict__ A, int lda, long sA,
        const float* __restrict__ B, int ldb, long sB,
        float* __restrict__ Cm, int ldc, long sC, int N, int K,
        const float* __restrict__ bias,
        const unsigned char* __restrict__ mask,
        const float* __restrict__ token,
        const float* __restrict__ e1, const float* __restrict__ e2,
        const float* __restrict__ e3, const float* __restrict__ e4)
{
    A += (long)blockIdx.z * sA;
    B += (long)blockIdx.z * sB;
    Cm += (long)blockIdx.z * sC;
    __shared__ float As[2][32][64];
    __shared__ float Bs[2][32][32];
    int tid = threadIdx.x;            // 128
    int bm = blockIdx.y * 64;
    int bn = blockIdx.x * 32;
    int tx = (tid & 7) * 4;           // n offset 0..28
    int ty = (tid >> 3) * 4;          // m offset 0..60
    int arow = tid >> 1, akq = (tid & 1) * 16;   // A: 4 quads/thread
    int brow = tid >> 2, bkq = (tid & 3) * 8;    // B^T: 2 quads/thread
    int bkk  = tid >> 2, bnn = (tid & 3) * 8;    // BKN=1 B: 2 quads/thread
    float acc[4][4] = {};
    float4 ra[4], rb[2];

    // prologue: tile 0 -> buffer 0
    #pragma unroll
    for (int j = 0; j < 4; j++)
        ra[j] = *(const float4*)&A[(size_t)(bm + arow) * lda + akq + j * 4];
    if (BKN) {
        #pragma unroll
        for (int j = 0; j < 2; j++) {
            rb[j] = make_float4(0.f, 0.f, 0.f, 0.f);
            if (bn + bnn + j * 4 < ldb)
                rb[j] = *(const float4*)&B[(size_t)bkk * ldb + bn + bnn + j * 4];
        }
    } else {
        #pragma unroll
        for (int j = 0; j < 2; j++)
            rb[j] = *(const float4*)&B[(size_t)(bn + brow) * ldb + bkq + j * 4];
    }
    #pragma unroll
    for (int j = 0; j < 4; j++) {
        As[0][akq + j * 4 + 0][arow] = ra[j].x; As[0][akq + j * 4 + 1][arow] = ra[j].y;
        As[0][akq + j * 4 + 2][arow] = ra[j].z; As[0][akq + j * 4 + 3][arow] = ra[j].w;
    }
    if (BKN) {
        #pragma unroll
        for (int j = 0; j < 2; j++)
            *(float4*)&Bs[0][bkk][bnn + j * 4] = rb[j];
    } else {
        #pragma unroll
        for (int j = 0; j < 2; j++) {
            Bs[0][bkq + j * 4 + 0][brow] = rb[j].x; Bs[0][bkq + j * 4 + 1][brow] = rb[j].y;
            Bs[0][bkq + j * 4 + 2][brow] = rb[j].z; Bs[0][bkq + j * 4 + 3][brow] = rb[j].w;
        }
    }
    __syncthreads();

    int p = 0;
    for (int k0 = 32; ; k0 += 32) {
        bool has_next = (k0 < K);
        if (has_next) {     // prefetch next tile into registers (hidden by compute)
            #pragma unroll
            for (int j = 0; j < 4; j++)
                ra[j] = *(const float4*)&A[(size_t)(bm + arow) * lda + k0 + akq + j * 4];
            if (BKN) {
                #pragma unroll
                for (int j = 0; j < 2; j++) {
                    rb[j] = make_float4(0.f, 0.f, 0.f, 0.f);
                    if (bn + bnn + j * 4 < ldb)
                        rb[j] = *(const float4*)&B[(size_t)(k0 + bkk) * ldb + bn + bnn + j * 4];
                }
            } else {
                #pragma unroll
                for (int j = 0; j < 2; j++)
                    rb[j] = *(const float4*)&B[(size_t)(bn + brow) * ldb + k0 + bkq + j * 4];
            }
        }
        #pragma unroll
        for (int kk = 0; kk < 32; kk++) {
            float4 a = *(const float4*)&As[p][kk][ty];
            float4 b = *(const float4*)&Bs[p][kk][tx];
            float am[4] = {a.x, a.y, a.z, a.w};
            float bv[4] = {b.x, b.y, b.z, b.w};
            #pragma unroll
            for (int i = 0; i < 4; i++)
                #pragma unroll
                for (int j = 0; j < 4; j++)
                    acc[i][j] = fmaf(am[i], bv[j], acc[i][j]);
        }
        if (!has_next) break;
        int q = p ^ 1;
        #pragma unroll
        for (int j = 0; j < 4; j++) {
            As[q][akq + j * 4 + 0][arow] = ra[j].x; As[q][akq + j * 4 + 1][arow] = ra[j].y;
            As[q][akq + j * 4 + 2][arow] = ra[j].z; As[q][akq + j * 4 + 3][arow] = ra[j].w;
        }
        if (BKN) {
            #pragma unroll
            for (int j = 0; j < 2; j++)
                *(float4*)&Bs[q][bkk][bnn + j * 4] = rb[j];
        } else {
            #pragma unroll
            for (int j = 0; j < 2; j++) {
                Bs[q][bkq + j * 4 + 0][brow] = rb[j].x; Bs[q][bkq + j * 4 + 1][brow] = rb[j].y;
                Bs[q][bkq + j * 4 + 2][brow] = rb[j].z; Bs[q][bkq + j * 4 + 3][brow] = rb[j].w;
            }
        }
        __syncthreads();
        p = q;
    }

    const bool vec = ((N & 3) == 0);
    #pragma unroll
    for (int i = 0; i < 4; i++) {
        int row = bm + ty + i;
        float v4[4];
        #pragma unroll
        for (int j = 0; j < 4; j++) {
            int col = bn + tx + j;
            float v = acc[i][j];
            if (EPI == EPI_PE) {
                v += bias[col];
                v += g_pe[(row & (T_ - 1)) * D_ + col];
            } else if (EPI == EPI_GELU) {
                v += bias[col];
                v = 0.5f * v * (1.f + erff(v * 0.70710678118654752f));
            } else if (EPI == EPI_SIGMASK) {
                v += bias[col];
                v = 1.f / (1.f + expf(-v));
                if (mask[row]) v = token[col];
            } else if (EPI == EPI_TMSEL) {
                if (!mask[row]) {
                    float m = v, a = 0.f;
                    for (int dd = 0; dd < D_; dd++) {
                        float u = fmaf(m, e1[dd], e2[dd]);
                        float g = 0.5f * u * (1.f + erff(u * 0.70710678118654752f));
                        a = fmaf(g, e3[dd], a);
                    }
                    v = 1.f / (1.f + expf(-(a + e4[0])));
                }
            } else if (EPI == EPI_ADDEX) {
                // mtd = ex + Wsub@delta  (irfft(rfft(ex)) == ex + masked delta)
                v += g_ex[((long)blockIdx.z * T_ + row) * D_ + col];
            }
            v4[j] = v;
        }
        if (vec) {
            *(float4*)&Cm[(size_t)row * ldc + bn + tx] =
                make_float4(v4[0], v4[1], v4[2], v4[3]);
        } else {
            #pragma unroll
            for (int j = 0; j < 4; j++) {
                int col = bn + tx + j;
                if (col < N) Cm[(size_t)row * ldc + col] = v4[j];
            }
        }
    }
}

// ---------------- windowed-variance score: one block per (b,t) -----------------
__global__ void score_kernel() {
    int bt = blockIdx.x;
    int b = bt >> 9, t = bt & 511;
    int tid = threadIdx.x;            // 256
    int t0 = t - (WIN_ - 1); if (t0 < 0) t0 = 0;
    float denom = (float)((t + 1 < WIN_) ? (t + 1) : WIN_);
    float num = 0.f, den = 0.f;
    for (int d = tid; d < D_; d += 256) {
        float s1 = 0.f, s2 = 0.f;
        const float* p = &g_ex[((size_t)b * T_ + t0) * D_ + d];
        for (int tt = t0; tt <= t; tt++) {
            float v = *p; p += D_;
            s1 += v;
            s2 = fmaf(v, v, s2);
        }
        float m1 = s1 / denom;
        num += s2 / denom - m1 * m1;
        den += m1;
    }
    __shared__ float sn[256], sd[256];
    sn[tid] = num; sd[tid] = den; __syncthreads();
    for (int s = 128; s > 0; s >>= 1) {
        if (tid < s) { sn[tid] += sn[tid + s]; sd[tid] += sd[tid + s]; }
        __syncthreads();
    }
    if (tid == 0) g_score[bt] = sn[0] / (sd[0] + 1e-6f);
}

// ---------------- top-k via rank selection (lax.top_k stable-desc semantics) ---
__global__ void topk_kernel(const float* __restrict__ vals, int n, int k,
                            int* __restrict__ idx_out,
                            unsigned char* __restrict__ mask_out,
                            float* __restrict__ outf)
{
    int b = blockIdx.x;
    int tid = threadIdx.x;            // 512
    __shared__ float v[512];
    for (int i = tid; i < n; i += blockDim.x) v[i] = vals[b * n + i];
    if (tid < n) mask_out[b * n + tid] = 0;
    __syncthreads();
    if (tid < n) {
        float x = v[tid];
        int rank = 0;
        for (int j = 0; j < n; j++) {
            float y = v[j];
            rank += (y > x) || (y == x && j < tid);
        }
        if (rank < k) {
            idx_out[b * k + rank] = tid;
            outf[b * k + rank] = (float)tid;
            mask_out[b * n + tid] = 1;
        }
    }
}

// ---------------- magnitude mean over d: one block per (b,f) -------------------
__global__ void mag_kernel() {
    int bf = blockIdx.x;
    int b = bf / F_, f = bf % F_;
    int d = threadIdx.x;              // 512
    float cr = g_cf[((size_t)b * MR + f) * D_ + d];
    float ci = (f == 0 || f == 256) ? 0.f
             : g_cf[((size_t)b * MR + 256 + f) * D_ + d];
    float m = sqrtf(cr * cr + ci * ci);
    __shared__ float red[512];
    red[d] = m; __syncthreads();
    for (int s = 256; s > 0; s >>= 1) {
        if (d < s) red[d] += red[d + s];
        __syncthreads();
    }
    if (d == 0) g_mag[bf] = red[0] * (1.f / 512.f);
}

// ---------------- fused: freq top-k + tm mask + compacted masked-row list ------
__global__ void freqpost_kernel(float* __restrict__ out_fidx) {
    int b = blockIdx.x;
    int tid = threadIdx.x;            // 512
    __shared__ float v[512];
    // --- top-k on mag (n = F_) ---
    if (tid < F_) v[tid] = g_mag[b * F_ + tid];
    if (tid < F_) g_fmask[b * F_ + tid] = 0;
    if (tid < NDELTA) g_rowlist[b * NDELTA + tid] = -1;
    __syncthreads();
    if (tid < F_) {
        float x = v[tid];
        int rank = 0;
        for (int j = 0; j < F_; j++) {
            float y = v[j];
            rank += (y > x) || (y == x && j < tid);
        }
        if (rank < K_TOP) {
            g_fidx[b * K_TOP + rank] = tid;
            out_fidx[b * K_TOP + rank] = (float)tid;
            g_fmask[b * F_ + tid] = 1;
        }
    }
    __syncthreads();
    // --- tm = irfft(fmask) != 0   (t = tid) ---
    {
        const unsigned char* fm = &g_fmask[b * F_];
        int t = tid;
        float y = fm[0] ? 1.f : 0.f;
        for (int f = 1; f < 256; f++)
            if (fm[f]) y += 2.f * g_costab[(f * t) & 511];
        if (fm[256]) y += (t & 1) ? -1.f : 1.f;
        g_tm[b * T_ + t] = (y != 0.f) ? 1 : 0;
    }
    // --- rowlist scatter (f = tid) ---
    if (tid < F_ && g_fmask[b * F_ + tid]) {
        int f = tid;
        int rank = 0;
        for (int g2 = 0; g2 < f; g2++)
            if (g_fmask[b * F_ + g2]) rank += (g2 == 0 || g2 == 256) ? 1 : 2;
        g_rowlist[b * NDELTA + rank] = f;               // re row
        if (f >= 1 && f <= 255)
            g_rowlist[b * NDELTA + rank + 1] = 256 + f; // im row
    }
}

// ---------------- build delta (token - cf, masked rows) + gathered Widft cols --
__global__ void builddw_kernel(const float* __restrict__ f_tok_re,
                               const float* __restrict__ f_tok_im) {
    int i = blockIdx.x * blockDim.x + threadIdx.x;
    const int nD = B_ * NDELTA * D_;
    if (i < nD) {
        int b = i / (NDELTA * D_);
        int rem = i - b * NDELTA * D_;
        int j = rem >> 9, d = rem & 511;
        int r = g_rowlist[b * NDELTA + j];
        float v = 0.f;
        if (r >= 0) {
            float tok = (r <= 256) ? f_tok_re[d] : f_tok_im[d];
            v = tok - g_cf[((size_t)b * MR + r) * D_ + d];
        }
        g_delta[i] = v;
    } else {
        int k = i - nD;
        if (k < B_ * T_ * NDELTA) {
            int b = k / (T_ * NDELTA);
            int rem = k - b * T_ * NDELTA;
            int t = rem / NDELTA, j = rem % NDELTA;
            int r = g_rowlist[b * NDELTA + j];
            g_wsub[k] = (r >= 0) ? g_widft[t * KI + r] : 0.f;
        }
    }
}

// ---------------- launch ----------------
extern "C" void kernel_launch(void* const* d_in, const int* in_sizes, int n_in,
                              void* d_out, int out_size) {
    const float* x        = (const float*)d_in[0];
    const float* W_emb    = (const float*)d_in[1];
    const float* b_emb    = (const float*)d_in[2];
    const float* t_token  = (const float*)d_in[3];
    const float* tW1      = (const float*)d_in[4];
    const float* tb1      = (const float*)d_in[5];
    const float* tW2      = (const float*)d_in[6];
    const float* tb2      = (const float*)d_in[7];
    const float* f_tok_re = (const float*)d_in[8];
    const float* f_tok_im = (const float*)d_in[9];
    const float* fW1      = (const float*)d_in[10];
    const float* fb1      = (const float*)d_in[11];
    const float* fW2      = (const float*)d_in[12];
    const float* fb2      = (const float*)d_in[13];
    float* out = (float*)d_out;

    // output packing: out_t [B,T,D] | tidx [B,51] | out_f [B,T,C] | fidx [B,51]
    float* out_t    = out;
    float* out_tidx = out + (size_t)B_ * T_ * D_;
    float* out_f    = out_tidx + B_ * K_TOP;
    float* out_fidx = out_f + (size_t)B_ * T_ * C_;

    float *p_ex, *p_h, *p_mtd, *p_score, *p_xpad, *p_wpad;
    float *p_wdft, *p_widft, *p_cf, *p_delta, *p_wsub;
    int *p_tidx;
    unsigned char *p_tmask, *p_tm;
    cudaGetSymbolAddress((void**)&p_ex,    g_ex);
    cudaGetSymbolAddress((void**)&p_h,     g_h);
    cudaGetSymbolAddress((void**)&p_mtd,   g_mtd);
    cudaGetSymbolAddress((void**)&p_score, g_score);
    cudaGetSymbolAddress((void**)&p_xpad,  g_xpad);
    cudaGetSymbolAddress((void**)&p_wpad,  g_wpad);
    cudaGetSymbolAddress((void**)&p_wdft,  g_wdft);
    cudaGetSymbolAddress((void**)&p_widft, g_widft);
    cudaGetSymbolAddress((void**)&p_cf,    g_cf);
    cudaGetSymbolAddress((void**)&p_delta, g_delta);
    cudaGetSymbolAddress((void**)&p_wsub,  g_wsub);
    cudaGetSymbolAddress((void**)&p_tidx,  g_tidx);
    cudaGetSymbolAddress((void**)&p_tmask, g_tmask);
    cudaGetSymbolAddress((void**)&p_tm,    g_tm);

    if (!g_sB) {
        cudaStreamCreateWithFlags(&g_sB, cudaStreamNonBlocking);
        cudaStreamCreateWithFlags(&g_sC, cudaStreamNonBlocking);
        cudaEventCreateWithFlags(&g_evStart, cudaEventDisableTiming);
        cudaEventCreateWithFlags(&g_evFork, cudaEventDisableTiming);
        cudaEventCreateWithFlags(&g_evJoin, cudaEventDisableTiming);
        cudaEventCreateWithFlags(&g_evC, cudaEventDisableTiming);
    }

    // ---- legal capture fork at t=0 ----
    cudaEventRecord(g_evStart, 0);
    cudaStreamWaitEvent(g_sB, g_evStart, 0);

    // DFT weight tables on g_sB (input-independent; overlaps prologue + GEMM1)
    init_wdft_kernel<<<(MR * T_ + T_ * KI + 255) / 256, 256, 0, g_sB>>>();

    // ---- prologue on stream 0 ----
    init_div_kernel<<<1, 512>>>();
    prep_kernel<<<(T_ * D_ + (B_ * T_ + D_) * KPAD + 255) / 256, 256>>>(x, W_emb);

    // ex = x * W_emb^T + b_emb + PE      (padded K=288)
    sgemm6_kernel<EPI_PE, 0><<<dim3(D_ / 32, B_ * T_ / 64), 128>>>(
        p_xpad, KPAD, 0, p_wpad, KPAD, 0, p_ex, D_, 0, D_, KPAD,
        b_emb, nullptr, nullptr, nullptr, nullptr, nullptr, nullptr);

    // ---- fork after ex ----
    cudaEventRecord(g_evFork, 0);
    cudaStreamWaitEvent(g_sB, g_evFork, 0);
    cudaStreamWaitEvent(g_sC, g_evFork, 0);

    // ---- path C: score + temporal top-k (overlaps h-GEMM) ----
    score_kernel<<<B_ * T_, 256, 0, g_sC>>>();
    topk_kernel<<<B_, 512, 0, g_sC>>>(p_score, T_, K_TOP, p_tidx, p_tmask, out_tidx);
    cudaEventRecord(g_evC, g_sC);

    // ---- path B (frequency) on g_sB ----
    {
        // cf[b] = Wdft[512,512] @ ex[b][512,512]   (packed re/im rows)
        sgemm6_kernel<EPI_NONE, 1><<<dim3(D_ / 32, MR / 64, B_), 128, 0, g_sB>>>(
            p_wdft, T_, 0, p_ex, D_, (long)T_ * D_, p_cf, D_, (long)MR * D_, D_, T_,
            nullptr, nullptr, nullptr, nullptr, nullptr, nullptr, nullptr);
        mag_kernel<<<B_ * F_, 512, 0, g_sB>>>();
        freqpost_kernel<<<B_, 512, 0, g_sB>>>(out_fidx);
        builddw_kernel<<<(B_ * NDELTA * D_ + B_ * T_ * NDELTA + 255) / 256, 256, 0, g_sB>>>(
            f_tok_re, f_tok_im);
        // mtd[b] = ex[b] + Wsub[b][512,128] @ delta[b][128,512]
        sgemm6_kernel<EPI_ADDEX, 1><<<dim3(D_ / 32, T_ / 64, B_), 128, 0, g_sB>>>(
            p_wsub, NDELTA, (long)T_ * NDELTA,
            p_delta, D_, (long)NDELTA * D_,
            p_mtd, D_, (long)T_ * D_, D_, NDELTA,
            nullptr, nullptr, nullptr, nullptr, nullptr, nullptr, nullptr);
        // out_f = tmsel(mtd @ W_emb)   (fused mx + outf)
        sgemm6_kernel<EPI_TMSEL, 1><<<dim3((C_ + 31) / 32, B_ * T_ / 64), 128, 0, g_sB>>>(
            p_mtd, D_, 0, p_wpad, KPAD, 0, out_f, C_, 0, C_, D_,
            nullptr, p_tm, nullptr, fW1, fb1, fW2, fb2);
        cudaEventRecord(g_evJoin, g_sB);
    }

    // ---- path A (temporal GEMMs) on stream 0 ----
    // h = gelu(ex * tW1^T + tb1)   — independent of score/topk
    sgemm6_kernel<EPI_GELU, 0><<<dim3(D_ / 32, B_ * T_ / 64), 128>>>(
        p_ex, D_, 0, tW1, D_, 0, p_h, D_, 0, D_, D_,
        tb1, nullptr, nullptr, nullptr, nullptr, nullptr, nullptr);
    // out_t = tmask ? t_token : sigmoid(h * tW2^T + tb2)  — needs tmask from path C
    cudaStreamWaitEvent(0, g_evC, 0);
    sgemm6_kernel<EPI_SIGMASK, 0><<<dim3(D_ / 32, B_ * T_ / 64), 128>>>(
        p_h, D_, 0, tW2, D_, 0, out_t, D_, 0, D_, D_,
        tb2, p_tmask, t_token, nullptr, nullptr, nullptr, nullptr);

    // ---- join ----
    cudaStreamWaitEvent(0, g_evJoin, 0);
}